// round 12
// baseline (speedup 1.0000x reference)
#include <cuda_runtime.h>
#include <cuda_fp16.h>
#include <cstdint>

// ---------------------------------------------------------------------------
// Fused LayerNorm-LSTM cell, sm_100 legacy tensor path.
//   Kernel 0: convert x,h -> g_A, Wih,Whh -> g_W (fp16, k-permuted).
//   Kernel 1: v = A @ W^T via mma.sync.m16n8k16.f16 (rt=16 floor).
//             Epilogue: +bias, per-row partial LN stats -> g_pstats,
//             v stored fp16 -> g_Vh.
//   Kernel 2: LN (precomputed stats) + LSTM + LN -> out.
// ---------------------------------------------------------------------------

#define BM 128
#define BN 128
#define BKH 64                          // k halfs per stage (128 B per row)
#define NS 3
#define NT 32                           // 2048 / 64
#define A_BYTES (BM * 128)              // 16384
#define STAGE_BYTES ((BM + BN) * 128)   // 32768
#define SMEM_SZ (NS * STAGE_BYTES + 1024)   // 99328

__device__ __half g_Vh[4096u * 4096u];      // 32 MB: v + bias, fp16
__device__ float  g_pstats[4096u * 32u * 2u]; // 1 MB: per (row, n-tile) sum/sumsq
__device__ __half g_A[4096u * 2048u];       // 16 MB fp16 [x|h], k-permuted
__device__ __half g_W[4096u * 2048u];       // 16 MB fp16 [Wih|Whh], k-permuted

// ---- helpers ---------------------------------------------------------------

__device__ __forceinline__ uint32_t s2u(const void* p) {
    return (uint32_t)__cvta_generic_to_shared(p);
}
__device__ __forceinline__ void cp_async16(uint32_t dst, const void* src) {
    asm volatile("cp.async.cg.shared.global [%0], [%1], 16;\n" :: "r"(dst), "l"(src));
}
__device__ __forceinline__ void cp_commit() {
    asm volatile("cp.async.commit_group;\n" ::: "memory");
}
template <int N> __device__ __forceinline__ void cp_wait() {
    asm volatile("cp.async.wait_group %0;\n" :: "n"(N) : "memory");
}
__device__ __forceinline__ void lds128(uint32_t* v, uint32_t a) {
    asm volatile("ld.shared.v4.b32 {%0,%1,%2,%3}, [%4];"
                 : "=r"(v[0]), "=r"(v[1]), "=r"(v[2]), "=r"(v[3]) : "r"(a));
}
__device__ __forceinline__ void mma_f16(float* d, uint32_t a0, uint32_t a1,
                                        uint32_t a2, uint32_t a3,
                                        uint32_t b0, uint32_t b1) {
    asm volatile(
        "mma.sync.aligned.m16n8k16.row.col.f32.f16.f16.f32 "
        "{%0,%1,%2,%3}, {%4,%5,%6,%7}, {%8,%9}, {%0,%1,%2,%3};\n"
        : "+f"(d[0]), "+f"(d[1]), "+f"(d[2]), "+f"(d[3])
        : "r"(a0), "r"(a1), "r"(a2), "r"(a3), "r"(b0), "r"(b1));
}

// ---- Kernel 0: fp16 convert + k-permute, 1 thread per 16B output -----------
// Output quarter i of a 32-half block holds source floats in order
// {2i, 2i+1, 2i+8, 2i+9, 2i+16, 2i+17, 2i+24, 2i+25}.

__global__ __launch_bounds__(256)
void tohalf(const float* __restrict__ x, const float* __restrict__ h,
            const float* __restrict__ Wih, const float* __restrict__ Whh) {
    const uint32_t q = blockIdx.x * 256u + threadIdx.x;     // 0 .. 2M-1
    const uint32_t tensor = q >> 20;                        // 0=A, 1=W
    const uint32_t r = q & 0xFFFFFu;
    const uint32_t blk = r >> 2;
    const uint32_t i = r & 3u;
    const uint32_t row = blk >> 6;
    const uint32_t chunk = blk & 63u;

    const float* src;
    __half* dst;
    if (tensor == 0) {
        src = (chunk < 32u) ? x + (size_t)row * 1024 + chunk * 32
                            : h + (size_t)row * 1024 + (chunk - 32u) * 32;
        dst = g_A + (size_t)row * 2048 + chunk * 32;
    } else {
        src = (chunk < 32u) ? Wih + (size_t)row * 1024 + chunk * 32
                            : Whh + (size_t)row * 1024 + (chunk - 32u) * 32;
        dst = g_W + (size_t)row * 2048 + chunk * 32;
    }

    const float2* p = (const float2*)src + i;
    float2 a = p[0], b = p[4], c2 = p[8], d = p[12];
    union { __half2 h2[4]; uint4 u; } o;
    o.h2[0] = __float22half2_rn(a);
    o.h2[1] = __float22half2_rn(b);
    o.h2[2] = __float22half2_rn(c2);
    o.h2[3] = __float22half2_rn(d);
    ((uint4*)dst)[i] = o.u;
}

// ---- Kernel 1: fp16 GEMM + bias + stats epilogue ----------------------------

__global__ __launch_bounds__(256, 2)
void gemm_f16(const __half* __restrict__ gA, const __half* __restrict__ gW,
              const float* __restrict__ b_ih) {
    extern __shared__ float dsm[];
    const uint32_t dyn0 = s2u(dsm);
    const uint32_t base = (dyn0 + 1023u) & ~1023u;

    const int tid  = threadIdx.x;
    const int warp = tid >> 5;
    const int lane = tid & 31;
    const int g    = lane >> 2;               // 0..7
    const int t4   = lane & 3;                // 0..3
    const int wm = (warp & 1) * 64;           // 64x32 warp tile
    const int wn = (warp >> 1) * 32;
    const int bm0 = blockIdx.y * BM;
    const int bn0 = blockIdx.x * BN;
    const uint32_t gpar = (uint32_t)(g & 1);

    float acc[4][4][4];
    #pragma unroll
    for (int i = 0; i < 4; i++)
        #pragma unroll
        for (int j = 0; j < 4; j++)
            #pragma unroll
            for (int k = 0; k < 4; k++) acc[i][j][k] = 0.f;

    const int lrow = tid >> 1;
    const int lc0  = (tid & 1) * 4;
    const uint32_t lsw = (uint32_t)(lrow & 1) << 2;

    auto issue_loads = [&](int kt) {
        const uint32_t sb = base + (uint32_t)(kt % NS) * STAGE_BYTES;
        const __half* arow = gA + (size_t)(bm0 + lrow) * 2048 + kt * BKH;
        const __half* brow = gW + (size_t)(bn0 + lrow) * 2048 + kt * BKH;
        #pragma unroll
        for (int j = 0; j < 4; j++) {
            int c = lc0 + j;
            uint32_t coff = ((uint32_t)c ^ lsw) * 16u;
            cp_async16(sb + (uint32_t)lrow * 128u + coff,           arow + c * 8);
            cp_async16(sb + A_BYTES + (uint32_t)lrow * 128u + coff, brow + c * 8);
        }
        cp_commit();
    };

    issue_loads(0); issue_loads(1);

    for (int kt = 0; kt < NT; kt++) {
        if (kt < NT - 1) cp_wait<1>();
        else             cp_wait<0>();
        __syncthreads();

        if (kt + NS - 1 < NT) issue_loads(kt + NS - 1);

        const uint32_t sA = base + (uint32_t)(kt % NS) * STAGE_BYTES;
        const uint32_t sB = sA + A_BYTES;
        const uint32_t tof = (uint32_t)t4 * 16u;

        #pragma unroll
        for (int i = 0; i < 2; i++) {
            const uint32_t ie = ((uint32_t)i ^ gpar) * 64u;

            uint32_t B[4][4];
            #pragma unroll
            for (int nt = 0; nt < 4; nt++)
                lds128(B[nt], sB + (uint32_t)(wn + nt * 8 + g) * 128u + ie + tof);

            #pragma unroll
            for (int mh = 0; mh < 2; mh++) {
                uint32_t A0[2][4], A8[2][4];
                #pragma unroll
                for (int m2 = 0; m2 < 2; m2++) {
                    uint32_t ad = sA + (uint32_t)(wm + (mh * 2 + m2) * 16 + g) * 128u + ie + tof;
                    lds128(A0[m2], ad);
                    lds128(A8[m2], ad + 8 * 128);
                }
                #pragma unroll
                for (int s = 0; s < 2; s++)
                    #pragma unroll
                    for (int m2 = 0; m2 < 2; m2++)
                        #pragma unroll
                        for (int nt = 0; nt < 4; nt++)
                            mma_f16(acc[mh * 2 + m2][nt],
                                    A0[m2][2 * s], A8[m2][2 * s],
                                    A0[m2][2 * s + 1], A8[m2][2 * s + 1],
                                    B[nt][2 * s], B[nt][2 * s + 1]);
            }
        }
    }

    // ---- epilogue: +bias, fp16 store, per-row partial stats ----
    __syncthreads();                          // all smem stage reads done

    float bnv[4][2];
    #pragma unroll
    for (int nt = 0; nt < 4; nt++) {
        int n = bn0 + wn + nt * 8 + t4 * 2;
        bnv[nt][0] = b_ih[n];
        bnv[nt][1] = b_ih[n + 1];
    }

    float rs[4][2], rss[4][2];
    #pragma unroll
    for (int mt = 0; mt < 4; mt++) {
        #pragma unroll
        for (int vh = 0; vh < 2; vh++) {
            float s = 0.f, q = 0.f;
            #pragma unroll
            for (int nt = 0; nt < 4; nt++) {
                float v0 = acc[mt][nt][vh * 2]     + bnv[nt][0];
                float v1 = acc[mt][nt][vh * 2 + 1] + bnv[nt][1];
                acc[mt][nt][vh * 2]     = v0;
                acc[mt][nt][vh * 2 + 1] = v1;
                s += v0 + v1;
                q += v0 * v0 + v1 * v1;
            }
            rs[mt][vh] = s; rss[mt][vh] = q;
        }
    }

    // fp16 store of v+bias
    #pragma unroll
    for (int mt = 0; mt < 4; mt++) {
        #pragma unroll
        for (int nt = 0; nt < 4; nt++) {
            int m = bm0 + wm + mt * 16 + g;
            int n = bn0 + wn + nt * 8 + t4 * 2;
            *(__half2*)&g_Vh[(size_t)m * 4096 + n] =
                __floats2half2_rn(acc[mt][nt][0], acc[mt][nt][1]);
            *(__half2*)&g_Vh[(size_t)(m + 8) * 4096 + n] =
                __floats2half2_rn(acc[mt][nt][2], acc[mt][nt][3]);
        }
    }

    // quad reduce (lanes t4=0..3 share rows)
    #pragma unroll
    for (int mt = 0; mt < 4; mt++)
        #pragma unroll
        for (int vh = 0; vh < 2; vh++) {
            rs[mt][vh]  += __shfl_xor_sync(0xffffffffu, rs[mt][vh],  1);
            rs[mt][vh]  += __shfl_xor_sync(0xffffffffu, rs[mt][vh],  2);
            rss[mt][vh] += __shfl_xor_sync(0xffffffffu, rss[mt][vh], 1);
            rss[mt][vh] += __shfl_xor_sync(0xffffffffu, rss[mt][vh], 2);
        }

    // per-wslot smem slices (deterministic, no atomics): sbuf[4][128][2]
    float* sbuf = dsm;
    const int wslot = warp >> 1;
    if (t4 == 0) {
        #pragma unroll
        for (int mt = 0; mt < 4; mt++)
            #pragma unroll
            for (int vh = 0; vh < 2; vh++) {
                int r = wm + mt * 16 + vh * 8 + g;
                sbuf[(wslot * 128 + r) * 2 + 0] = rs[mt][vh];
                sbuf[(wslot * 128 + r) * 2 + 1] = rss[mt][vh];
            }
    }
    __syncthreads();
    {
        int r = tid >> 1, cmp = tid & 1;
        float t = sbuf[(0 * 128 + r) * 2 + cmp] + sbuf[(1 * 128 + r) * 2 + cmp]
                + sbuf[(2 * 128 + r) * 2 + cmp] + sbuf[(3 * 128 + r) * 2 + cmp];
        g_pstats[((size_t)(bm0 + r) * 32 + blockIdx.x) * 2 + cmp] = t;
    }
}

// ---- Kernel 2: LN (precomputed stats) + LSTM + LN ---------------------------

__device__ __forceinline__ float sigm(float v) {
    return __fdividef(1.f, 1.f + __expf(-v));
}
__device__ __forceinline__ float tanh_f(float v) {
    return fmaf(2.f, sigm(2.f * v), -1.f);
}

__global__ __launch_bounds__(256)
void ln_lstm(const float* __restrict__ c,
             const float* __restrict__ gamma_ifgo, const float* __restrict__ beta_ifgo,
             const float* __restrict__ gamma_c,    const float* __restrict__ beta_c,
             float* __restrict__ out) {
    __shared__ float2 gstat[4];
    __shared__ float red2[8][2];

    const int b   = blockIdx.x;
    const int tid = threadIdx.x;
    const int w   = tid >> 5;

    // gate stats from g_pstats (4 threads, 8 tiles each)
    if (tid < 4) {
        const float2* p = (const float2*)g_pstats + (size_t)b * 32 + tid * 8;
        float S = 0.f, Q = 0.f;
        #pragma unroll
        for (int i = 0; i < 8; i++) { float2 v = p[i]; S += v.x; Q += v.y; }
        float mean = S * (1.f / 1024.f);
        float var  = fmaxf(Q - S * mean, 0.f) * (1.f / 1023.f);
        gstat[tid] = make_float2(mean, 1.f / (sqrtf(var) + 1e-6f));
    }
    __syncthreads();

    const __half* vb = g_Vh + (size_t)b * 4096;
    float4 gate[4];
    #pragma unroll
    for (int g = 0; g < 4; g++) {
        uint2 raw = ((const uint2*)(vb + g * 1024))[tid];
        float2 p0 = __half22float2(*(__half2*)&raw.x);
        float2 p1 = __half22float2(*(__half2*)&raw.y);
        float mean = gstat[g].x, inv = gstat[g].y;
        float4 ga = ((const float4*)gamma_ifgo)[g * 256 + tid];
        float4 be = ((const float4*)beta_ifgo)[g * 256 + tid];
        gate[g].x = ga.x * (p0.x - mean) * inv + be.x;
        gate[g].y = ga.y * (p0.y - mean) * inv + be.y;
        gate[g].z = ga.z * (p1.x - mean) * inv + be.z;
        gate[g].w = ga.w * (p1.y - mean) * inv + be.w;
    }

    float4 ci = ((const float4*)(c + (size_t)b * 1024))[tid];
    float4 cc;
    cc.x = ci.x * sigm(gate[1].x + 1.f) + sigm(gate[0].x) * tanh_f(gate[2].x);
    cc.y = ci.y * sigm(gate[1].y + 1.f) + sigm(gate[0].y) * tanh_f(gate[2].y);
    cc.z = ci.z * sigm(gate[1].z + 1.f) + sigm(gate[0].z) * tanh_f(gate[2].z);
    cc.w = ci.w * sigm(gate[1].w + 1.f) + sigm(gate[0].w) * tanh_f(gate[2].w);

    float s2  = cc.x + cc.y + cc.z + cc.w;
    float ss2 = cc.x * cc.x + cc.y * cc.y + cc.z * cc.z + cc.w * cc.w;
    #pragma unroll
    for (int o = 16; o > 0; o >>= 1) {
        s2  += __shfl_xor_sync(0xffffffffu, s2,  o);
        ss2 += __shfl_xor_sync(0xffffffffu, ss2, o);
    }
    if ((tid & 31) == 0) { red2[w][0] = s2; red2[w][1] = ss2; }
    __syncthreads();
    float S = 0.f, SS = 0.f;
    #pragma unroll
    for (int i = 0; i < 8; i++) { S += red2[i][0]; SS += red2[i][1]; }
    float mean = S * (1.f / 1024.f);
    float var  = fmaxf(SS - S * mean, 0.f) * (1.f / 1023.f);
    float inv  = 1.f / (sqrtf(var) + 1e-6f);

    float4 gc = ((const float4*)gamma_c)[tid];
    float4 bc = ((const float4*)beta_c)[tid];
    float4 nc, nh;
    nc.x = gc.x * (cc.x - mean) * inv + bc.x;  nh.x = tanh_f(nc.x) * sigm(gate[3].x);
    nc.y = gc.y * (cc.y - mean) * inv + bc.y;  nh.y = tanh_f(nc.y) * sigm(gate[3].y);
    nc.z = gc.z * (cc.z - mean) * inv + bc.z;  nh.z = tanh_f(nc.z) * sigm(gate[3].z);
    nc.w = gc.w * (cc.w - mean) * inv + bc.w;  nh.w = tanh_f(nc.w) * sigm(gate[3].w);

    ((float4*)out)[(size_t)b * 256 + tid]                      = nh;
    ((float4*)out)[(size_t)4096 * 256 + (size_t)b * 256 + tid] = nc;
}

// ---- launch ----------------------------------------------------------------

extern "C" void kernel_launch(void* const* d_in, const int* in_sizes, int n_in,
                              void* d_out, int out_size) {
    const float* x     = (const float*)d_in[0];
    const float* h     = (const float*)d_in[1];
    const float* c     = (const float*)d_in[2];
    const float* Wih   = (const float*)d_in[3];
    const float* bih   = (const float*)d_in[4];
    const float* Whh   = (const float*)d_in[5];
    const float* gifgo = (const float*)d_in[6];
    const float* bifgo = (const float*)d_in[7];
    const float* gc    = (const float*)d_in[8];
    const float* bc    = (const float*)d_in[9];
    float* out = (float*)d_out;

    __half *gA, *gW;
    cudaGetSymbolAddress((void**)&gA, g_A);
    cudaGetSymbolAddress((void**)&gW, g_W);

    cudaFuncSetAttribute(gemm_f16, cudaFuncAttributeMaxDynamicSharedMemorySize, SMEM_SZ);

    tohalf<<<8192, 256>>>(x, h, Wih, Whh);
    dim3 grid(4096 / BN, 4096 / BM);            // 32 x 32
    gemm_f16<<<grid, 256, SMEM_SZ>>>(gA, gW, bih);
    ln_lstm<<<4096, 256>>>(c, gifgo, bifgo, gc, bc, out);
}

// round 13
// speedup vs baseline: 1.0184x; 1.0184x over previous
#include <cuda_runtime.h>
#include <cuda_fp16.h>
#include <cstdint>

// ---------------------------------------------------------------------------
// Fused LayerNorm-LSTM cell, sm_100 legacy tensor path.
//   Kernel 0: convert x,h -> g_A, Wih,Whh -> g_W (fp16, k-permuted).
//   Kernel 1: v = A @ W^T via mma.sync.m16n8k16.f16 -> g_Vh (fp16 store).
//             R11 structure exactly; only the store width changed.
//   Kernel 2: 4x LN + LSTM elementwise + LN -> out (reads fp16 v + bias).
// ---------------------------------------------------------------------------

#define BM 128
#define BN 128
#define BKH 64                          // k halfs per stage (128 B per row)
#define NS 3
#define NT 32                           // 2048 / 64
#define A_BYTES (BM * 128)              // 16384
#define STAGE_BYTES ((BM + BN) * 128)   // 32768
#define SMEM_SZ (NS * STAGE_BYTES + 1024)   // 99328

__device__ __half g_Vh[4096u * 4096u];  // 32 MB: v (pre-bias), fp16
__device__ __half g_A[4096u * 2048u];   // 16 MB fp16 [x|h], k-permuted
__device__ __half g_W[4096u * 2048u];   // 16 MB fp16 [Wih|Whh], k-permuted

// ---- helpers ---------------------------------------------------------------

__device__ __forceinline__ uint32_t s2u(const void* p) {
    return (uint32_t)__cvta_generic_to_shared(p);
}
__device__ __forceinline__ void cp_async16(uint32_t dst, const void* src) {
    asm volatile("cp.async.cg.shared.global [%0], [%1], 16;\n" :: "r"(dst), "l"(src));
}
__device__ __forceinline__ void cp_commit() {
    asm volatile("cp.async.commit_group;\n" ::: "memory");
}
template <int N> __device__ __forceinline__ void cp_wait() {
    asm volatile("cp.async.wait_group %0;\n" :: "n"(N) : "memory");
}
__device__ __forceinline__ void lds128(uint32_t* v, uint32_t a) {
    asm volatile("ld.shared.v4.b32 {%0,%1,%2,%3}, [%4];"
                 : "=r"(v[0]), "=r"(v[1]), "=r"(v[2]), "=r"(v[3]) : "r"(a));
}
__device__ __forceinline__ void mma_f16(float* d, uint32_t a0, uint32_t a1,
                                        uint32_t a2, uint32_t a3,
                                        uint32_t b0, uint32_t b1) {
    asm volatile(
        "mma.sync.aligned.m16n8k16.row.col.f32.f16.f16.f32 "
        "{%0,%1,%2,%3}, {%4,%5,%6,%7}, {%8,%9}, {%0,%1,%2,%3};\n"
        : "+f"(d[0]), "+f"(d[1]), "+f"(d[2]), "+f"(d[3])
        : "r"(a0), "r"(a1), "r"(a2), "r"(a3), "r"(b0), "r"(b1));
}

// ---- Kernel 0: fp16 convert + k-permute, 1 thread per 16B output -----------
// Output quarter i of a 32-half block holds source floats in order
// {2i, 2i+1, 2i+8, 2i+9, 2i+16, 2i+17, 2i+24, 2i+25}.

__global__ __launch_bounds__(256)
void tohalf(const float* __restrict__ x, const float* __restrict__ h,
            const float* __restrict__ Wih, const float* __restrict__ Whh) {
    const uint32_t q = blockIdx.x * 256u + threadIdx.x;     // 0 .. 2M-1
    const uint32_t tensor = q >> 20;                        // 0=A, 1=W
    const uint32_t r = q & 0xFFFFFu;
    const uint32_t blk = r >> 2;
    const uint32_t i = r & 3u;
    const uint32_t row = blk >> 6;
    const uint32_t chunk = blk & 63u;

    const float* src;
    __half* dst;
    if (tensor == 0) {
        src = (chunk < 32u) ? x + (size_t)row * 1024 + chunk * 32
                            : h + (size_t)row * 1024 + (chunk - 32u) * 32;
        dst = g_A + (size_t)row * 2048 + chunk * 32;
    } else {
        src = (chunk < 32u) ? Wih + (size_t)row * 1024 + chunk * 32
                            : Whh + (size_t)row * 1024 + (chunk - 32u) * 32;
        dst = g_W + (size_t)row * 2048 + chunk * 32;
    }

    const float2* p = (const float2*)src + i;
    float2 a = p[0], b = p[4], c2 = p[8], d = p[12];
    union { __half2 h2[4]; uint4 u; } o;
    o.h2[0] = __float22half2_rn(a);
    o.h2[1] = __float22half2_rn(b);
    o.h2[2] = __float22half2_rn(c2);
    o.h2[3] = __float22half2_rn(d);
    ((uint4*)dst)[i] = o.u;
}

// ---- Kernel 1: fp16 GEMM, 2 CTAs/SM (R11 structure; fp16 store) -------------

__global__ __launch_bounds__(256, 2)
void gemm_f16(const __half* __restrict__ gA, const __half* __restrict__ gW) {
    extern __shared__ float dsm[];
    const uint32_t dyn0 = s2u(dsm);
    const uint32_t base = (dyn0 + 1023u) & ~1023u;

    const int tid  = threadIdx.x;
    const int warp = tid >> 5;
    const int lane = tid & 31;
    const int g    = lane >> 2;               // 0..7
    const int t4   = lane & 3;                // 0..3
    const int wm = (warp & 1) * 64;           // 64x32 warp tile
    const int wn = (warp >> 1) * 32;
    const int bm0 = blockIdx.y * BM;
    const int bn0 = blockIdx.x * BN;
    const uint32_t gpar = (uint32_t)(g & 1);

    float acc[4][4][4];
    #pragma unroll
    for (int i = 0; i < 4; i++)
        #pragma unroll
        for (int j = 0; j < 4; j++)
            #pragma unroll
            for (int k = 0; k < 4; k++) acc[i][j][k] = 0.f;

    const int lrow = tid >> 1;
    const int lc0  = (tid & 1) * 4;
    const uint32_t lsw = (uint32_t)(lrow & 1) << 2;

    auto issue_loads = [&](int kt) {
        const uint32_t sb = base + (uint32_t)(kt % NS) * STAGE_BYTES;
        const __half* arow = gA + (size_t)(bm0 + lrow) * 2048 + kt * BKH;
        const __half* brow = gW + (size_t)(bn0 + lrow) * 2048 + kt * BKH;
        #pragma unroll
        for (int j = 0; j < 4; j++) {
            int c = lc0 + j;
            uint32_t coff = ((uint32_t)c ^ lsw) * 16u;
            cp_async16(sb + (uint32_t)lrow * 128u + coff,           arow + c * 8);
            cp_async16(sb + A_BYTES + (uint32_t)lrow * 128u + coff, brow + c * 8);
        }
        cp_commit();
    };

    issue_loads(0); issue_loads(1);

    for (int kt = 0; kt < NT; kt++) {
        if (kt < NT - 1) cp_wait<1>();
        else             cp_wait<0>();
        __syncthreads();

        if (kt + NS - 1 < NT) issue_loads(kt + NS - 1);

        const uint32_t sA = base + (uint32_t)(kt % NS) * STAGE_BYTES;
        const uint32_t sB = sA + A_BYTES;
        const uint32_t tof = (uint32_t)t4 * 16u;

        #pragma unroll
        for (int i = 0; i < 2; i++) {
            const uint32_t ie = ((uint32_t)i ^ gpar) * 64u;

            uint32_t B[4][4];
            #pragma unroll
            for (int nt = 0; nt < 4; nt++)
                lds128(B[nt], sB + (uint32_t)(wn + nt * 8 + g) * 128u + ie + tof);

            #pragma unroll
            for (int mh = 0; mh < 2; mh++) {
                uint32_t A0[2][4], A8[2][4];
                #pragma unroll
                for (int m2 = 0; m2 < 2; m2++) {
                    uint32_t ad = sA + (uint32_t)(wm + (mh * 2 + m2) * 16 + g) * 128u + ie + tof;
                    lds128(A0[m2], ad);
                    lds128(A8[m2], ad + 8 * 128);
                }
                #pragma unroll
                for (int s = 0; s < 2; s++)
                    #pragma unroll
                    for (int m2 = 0; m2 < 2; m2++)
                        #pragma unroll
                        for (int nt = 0; nt < 4; nt++)
                            mma_f16(acc[mh * 2 + m2][nt],
                                    A0[m2][2 * s], A8[m2][2 * s],
                                    A0[m2][2 * s + 1], A8[m2][2 * s + 1],
                                    B[nt][2 * s], B[nt][2 * s + 1]);
            }
        }
    }

    // epilogue: direct fp16 STG of fragments (no extra syncs/smem)
    #pragma unroll
    for (int mt = 0; mt < 4; mt++) {
        #pragma unroll
        for (int nt = 0; nt < 4; nt++) {
            int m = bm0 + wm + mt * 16 + g;
            int n = bn0 + wn + nt * 8 + t4 * 2;
            *(__half2*)&g_Vh[(size_t)m * 4096 + n] =
                __floats2half2_rn(acc[mt][nt][0], acc[mt][nt][1]);
            *(__half2*)&g_Vh[(size_t)(m + 8) * 4096 + n] =
                __floats2half2_rn(acc[mt][nt][2], acc[mt][nt][3]);
        }
    }
}

// ---- Kernel 2: LayerNorms + LSTM elementwise --------------------------------

__device__ __forceinline__ float sigm(float v) {
    return __fdividef(1.f, 1.f + __expf(-v));
}
__device__ __forceinline__ float tanh_f(float v) {
    return fmaf(2.f, sigm(2.f * v), -1.f);
}

__global__ __launch_bounds__(256)
void ln_lstm(const float* __restrict__ c,
             const float* __restrict__ b_ih,
             const float* __restrict__ gamma_ifgo, const float* __restrict__ beta_ifgo,
             const float* __restrict__ gamma_c,    const float* __restrict__ beta_c,
             float* __restrict__ out) {
    __shared__ float red[8][8];
    __shared__ float red2[8][2];

    const int b   = blockIdx.x;
    const int tid = threadIdx.x;
    const int w   = tid >> 5;

    const __half* vb   = g_Vh + (size_t)b * 4096;
    const float4* bih4 = (const float4*)b_ih;

    float4 wv[4];
    float  s[4], ss[4];
    #pragma unroll
    for (int g = 0; g < 4; g++) {
        uint2 raw = ((const uint2*)(vb + g * 1024))[tid];
        float2 p0 = __half22float2(*(__half2*)&raw.x);
        float2 p1 = __half22float2(*(__half2*)&raw.y);
        float4 bb = bih4[g * 256 + tid];
        float4 t;
        t.x = p0.x + bb.x; t.y = p0.y + bb.y; t.z = p1.x + bb.z; t.w = p1.y + bb.w;
        wv[g] = t;
        s[g]  = t.x + t.y + t.z + t.w;
        ss[g] = t.x * t.x + t.y * t.y + t.z * t.z + t.w * t.w;
    }
    #pragma unroll
    for (int o = 16; o > 0; o >>= 1) {
        #pragma unroll
        for (int g = 0; g < 4; g++) {
            s[g]  += __shfl_xor_sync(0xffffffffu, s[g],  o);
            ss[g] += __shfl_xor_sync(0xffffffffu, ss[g], o);
        }
    }
    if ((tid & 31) == 0) {
        #pragma unroll
        for (int g = 0; g < 4; g++) { red[w][g * 2] = s[g]; red[w][g * 2 + 1] = ss[g]; }
    }
    __syncthreads();

    float4 gate[4];
    #pragma unroll
    for (int g = 0; g < 4; g++) {
        float S = 0.f, SS = 0.f;
        #pragma unroll
        for (int i = 0; i < 8; i++) { S += red[i][g * 2]; SS += red[i][g * 2 + 1]; }
        float mean = S * (1.f / 1024.f);
        float var  = fmaxf(SS - S * mean, 0.f) * (1.f / 1023.f);
        float inv  = 1.f / (sqrtf(var) + 1e-6f);
        float4 ga = ((const float4*)gamma_ifgo)[g * 256 + tid];
        float4 be = ((const float4*)beta_ifgo)[g * 256 + tid];
        gate[g].x = ga.x * (wv[g].x - mean) * inv + be.x;
        gate[g].y = ga.y * (wv[g].y - mean) * inv + be.y;
        gate[g].z = ga.z * (wv[g].z - mean) * inv + be.z;
        gate[g].w = ga.w * (wv[g].w - mean) * inv + be.w;
    }

    float4 ci = ((const float4*)(c + (size_t)b * 1024))[tid];
    float4 cc;
    cc.x = ci.x * sigm(gate[1].x + 1.f) + sigm(gate[0].x) * tanh_f(gate[2].x);
    cc.y = ci.y * sigm(gate[1].y + 1.f) + sigm(gate[0].y) * tanh_f(gate[2].y);
    cc.z = ci.z * sigm(gate[1].z + 1.f) + sigm(gate[0].z) * tanh_f(gate[2].z);
    cc.w = ci.w * sigm(gate[1].w + 1.f) + sigm(gate[0].w) * tanh_f(gate[2].w);

    float s2  = cc.x + cc.y + cc.z + cc.w;
    float ss2 = cc.x * cc.x + cc.y * cc.y + cc.z * cc.z + cc.w * cc.w;
    #pragma unroll
    for (int o = 16; o > 0; o >>= 1) {
        s2  += __shfl_xor_sync(0xffffffffu, s2,  o);
        ss2 += __shfl_xor_sync(0xffffffffu, ss2, o);
    }
    if ((tid & 31) == 0) { red2[w][0] = s2; red2[w][1] = ss2; }
    __syncthreads();
    float S = 0.f, SS = 0.f;
    #pragma unroll
    for (int i = 0; i < 8; i++) { S += red2[i][0]; SS += red2[i][1]; }
    float mean = S * (1.f / 1024.f);
    float var  = fmaxf(SS - S * mean, 0.f) * (1.f / 1023.f);
    float inv  = 1.f / (sqrtf(var) + 1e-6f);

    float4 gc = ((const float4*)gamma_c)[tid];
    float4 bc = ((const float4*)beta_c)[tid];
    float4 nc, nh;
    nc.x = gc.x * (cc.x - mean) * inv + bc.x;  nh.x = tanh_f(nc.x) * sigm(gate[3].x);
    nc.y = gc.y * (cc.y - mean) * inv + bc.y;  nh.y = tanh_f(nc.y) * sigm(gate[3].y);
    nc.z = gc.z * (cc.z - mean) * inv + bc.z;  nh.z = tanh_f(nc.z) * sigm(gate[3].z);
    nc.w = gc.w * (cc.w - mean) * inv + bc.w;  nh.w = tanh_f(nc.w) * sigm(gate[3].w);

    ((float4*)out)[(size_t)b * 256 + tid]                      = nh;
    ((float4*)out)[(size_t)4096 * 256 + (size_t)b * 256 + tid] = nc;
}

// ---- launch ----------------------------------------------------------------

extern "C" void kernel_launch(void* const* d_in, const int* in_sizes, int n_in,
                              void* d_out, int out_size) {
    const float* x     = (const float*)d_in[0];
    const float* h     = (const float*)d_in[1];
    const float* c     = (const float*)d_in[2];
    const float* Wih   = (const float*)d_in[3];
    const float* bih   = (const float*)d_in[4];
    const float* Whh   = (const float*)d_in[5];
    const float* gifgo = (const float*)d_in[6];
    const float* bifgo = (const float*)d_in[7];
    const float* gc    = (const float*)d_in[8];
    const float* bc    = (const float*)d_in[9];
    float* out = (float*)d_out;

    __half *gA, *gW;
    cudaGetSymbolAddress((void**)&gA, g_A);
    cudaGetSymbolAddress((void**)&gW, g_W);

    cudaFuncSetAttribute(gemm_f16, cudaFuncAttributeMaxDynamicSharedMemorySize, SMEM_SZ);

    tohalf<<<8192, 256>>>(x, h, Wih, Whh);
    dim3 grid(4096 / BN, 4096 / BM);            // 32 x 32
    gemm_f16<<<grid, 256, SMEM_SZ>>>(gA, gW);
    ln_lstm<<<4096, 256>>>(c, bih, gifgo, bifgo, gc, bc, out);
}

// round 14
// speedup vs baseline: 1.0327x; 1.0140x over previous
#include <cuda_runtime.h>
#include <cuda_fp16.h>
#include <cstdint>

// ---------------------------------------------------------------------------
// Fused LayerNorm-LSTM cell, sm_100 legacy tensor path.
//   Kernel 0: convert x,h -> g_A, Wih,Whh -> g_W (fp16, k-permuted).
//   Kernel 1: v = A @ W^T via mma.sync.m16n8k16.f16 -> g_V f32 (R11 exact).
//   Kernel 2: 4x LN + LSTM + LN -> out; 128 thr/block, 8 elem/thread.
// ---------------------------------------------------------------------------

#define BM 128
#define BN 128
#define BKH 64                          // k halfs per stage (128 B per row)
#define NS 3
#define NT 32                           // 2048 / 64
#define A_BYTES (BM * 128)              // 16384
#define STAGE_BYTES ((BM + BN) * 128)   // 32768
#define SMEM_SZ (NS * STAGE_BYTES + 1024)   // 99328

__device__ float  g_V[4096u * 4096u];   // 64 MB pre-LN gate activations
__device__ __half g_A[4096u * 2048u];   // 16 MB fp16 [x|h], k-permuted
__device__ __half g_W[4096u * 2048u];   // 16 MB fp16 [Wih|Whh], k-permuted

// ---- helpers ---------------------------------------------------------------

__device__ __forceinline__ uint32_t s2u(const void* p) {
    return (uint32_t)__cvta_generic_to_shared(p);
}
__device__ __forceinline__ void cp_async16(uint32_t dst, const void* src) {
    asm volatile("cp.async.cg.shared.global [%0], [%1], 16;\n" :: "r"(dst), "l"(src));
}
__device__ __forceinline__ void cp_commit() {
    asm volatile("cp.async.commit_group;\n" ::: "memory");
}
template <int N> __device__ __forceinline__ void cp_wait() {
    asm volatile("cp.async.wait_group %0;\n" :: "n"(N) : "memory");
}
__device__ __forceinline__ void lds128(uint32_t* v, uint32_t a) {
    asm volatile("ld.shared.v4.b32 {%0,%1,%2,%3}, [%4];"
                 : "=r"(v[0]), "=r"(v[1]), "=r"(v[2]), "=r"(v[3]) : "r"(a));
}
__device__ __forceinline__ void mma_f16(float* d, uint32_t a0, uint32_t a1,
                                        uint32_t a2, uint32_t a3,
                                        uint32_t b0, uint32_t b1) {
    asm volatile(
        "mma.sync.aligned.m16n8k16.row.col.f32.f16.f16.f32 "
        "{%0,%1,%2,%3}, {%4,%5,%6,%7}, {%8,%9}, {%0,%1,%2,%3};\n"
        : "+f"(d[0]), "+f"(d[1]), "+f"(d[2]), "+f"(d[3])
        : "r"(a0), "r"(a1), "r"(a2), "r"(a3), "r"(b0), "r"(b1));
}

// ---- Kernel 0: fp16 convert + k-permute, 1 thread per 16B output -----------

__global__ __launch_bounds__(256)
void tohalf(const float* __restrict__ x, const float* __restrict__ h,
            const float* __restrict__ Wih, const float* __restrict__ Whh) {
    const uint32_t q = blockIdx.x * 256u + threadIdx.x;     // 0 .. 2M-1
    const uint32_t tensor = q >> 20;                        // 0=A, 1=W
    const uint32_t r = q & 0xFFFFFu;
    const uint32_t blk = r >> 2;
    const uint32_t i = r & 3u;
    const uint32_t row = blk >> 6;
    const uint32_t chunk = blk & 63u;

    const float* src;
    __half* dst;
    if (tensor == 0) {
        src = (chunk < 32u) ? x + (size_t)row * 1024 + chunk * 32
                            : h + (size_t)row * 1024 + (chunk - 32u) * 32;
        dst = g_A + (size_t)row * 2048 + chunk * 32;
    } else {
        src = (chunk < 32u) ? Wih + (size_t)row * 1024 + chunk * 32
                            : Whh + (size_t)row * 1024 + (chunk - 32u) * 32;
        dst = g_W + (size_t)row * 2048 + chunk * 32;
    }

    const float2* p = (const float2*)src + i;
    float2 a = p[0], b = p[4], c2 = p[8], d = p[12];
    union { __half2 h2[4]; uint4 u; } o;
    o.h2[0] = __float22half2_rn(a);
    o.h2[1] = __float22half2_rn(b);
    o.h2[2] = __float22half2_rn(c2);
    o.h2[3] = __float22half2_rn(d);
    ((uint4*)dst)[i] = o.u;
}

// ---- Kernel 1: fp16 GEMM, 2 CTAs/SM (R11 exact, fp32 store) ------------------

__global__ __launch_bounds__(256, 2)
void gemm_f16(const __half* __restrict__ gA, const __half* __restrict__ gW) {
    extern __shared__ float dsm[];
    const uint32_t dyn0 = s2u(dsm);
    const uint32_t base = (dyn0 + 1023u) & ~1023u;

    const int tid  = threadIdx.x;
    const int warp = tid >> 5;
    const int lane = tid & 31;
    const int g    = lane >> 2;               // 0..7
    const int t4   = lane & 3;                // 0..3
    const int wm = (warp & 1) * 64;           // 64x32 warp tile
    const int wn = (warp >> 1) * 32;
    const int bm0 = blockIdx.y * BM;
    const int bn0 = blockIdx.x * BN;
    const uint32_t gpar = (uint32_t)(g & 1);

    float acc[4][4][4];
    #pragma unroll
    for (int i = 0; i < 4; i++)
        #pragma unroll
        for (int j = 0; j < 4; j++)
            #pragma unroll
            for (int k = 0; k < 4; k++) acc[i][j][k] = 0.f;

    const int lrow = tid >> 1;
    const int lc0  = (tid & 1) * 4;
    const uint32_t lsw = (uint32_t)(lrow & 1) << 2;

    auto issue_loads = [&](int kt) {
        const uint32_t sb = base + (uint32_t)(kt % NS) * STAGE_BYTES;
        const __half* arow = gA + (size_t)(bm0 + lrow) * 2048 + kt * BKH;
        const __half* brow = gW + (size_t)(bn0 + lrow) * 2048 + kt * BKH;
        #pragma unroll
        for (int j = 0; j < 4; j++) {
            int c = lc0 + j;
            uint32_t coff = ((uint32_t)c ^ lsw) * 16u;
            cp_async16(sb + (uint32_t)lrow * 128u + coff,           arow + c * 8);
            cp_async16(sb + A_BYTES + (uint32_t)lrow * 128u + coff, brow + c * 8);
        }
        cp_commit();
    };

    issue_loads(0); issue_loads(1);

    for (int kt = 0; kt < NT; kt++) {
        if (kt < NT - 1) cp_wait<1>();
        else             cp_wait<0>();
        __syncthreads();

        if (kt + NS - 1 < NT) issue_loads(kt + NS - 1);

        const uint32_t sA = base + (uint32_t)(kt % NS) * STAGE_BYTES;
        const uint32_t sB = sA + A_BYTES;
        const uint32_t tof = (uint32_t)t4 * 16u;

        #pragma unroll
        for (int i = 0; i < 2; i++) {
            const uint32_t ie = ((uint32_t)i ^ gpar) * 64u;

            uint32_t B[4][4];
            #pragma unroll
            for (int nt = 0; nt < 4; nt++)
                lds128(B[nt], sB + (uint32_t)(wn + nt * 8 + g) * 128u + ie + tof);

            #pragma unroll
            for (int mh = 0; mh < 2; mh++) {
                uint32_t A0[2][4], A8[2][4];
                #pragma unroll
                for (int m2 = 0; m2 < 2; m2++) {
                    uint32_t ad = sA + (uint32_t)(wm + (mh * 2 + m2) * 16 + g) * 128u + ie + tof;
                    lds128(A0[m2], ad);
                    lds128(A8[m2], ad + 8 * 128);
                }
                #pragma unroll
                for (int s = 0; s < 2; s++)
                    #pragma unroll
                    for (int m2 = 0; m2 < 2; m2++)
                        #pragma unroll
                        for (int nt = 0; nt < 4; nt++)
                            mma_f16(acc[mh * 2 + m2][nt],
                                    A0[m2][2 * s], A8[m2][2 * s],
                                    A0[m2][2 * s + 1], A8[m2][2 * s + 1],
                                    B[nt][2 * s], B[nt][2 * s + 1]);
            }
        }
    }

    #pragma unroll
    for (int mt = 0; mt < 4; mt++) {
        #pragma unroll
        for (int nt = 0; nt < 4; nt++) {
            int m = bm0 + wm + mt * 16 + g;
            int n = bn0 + wn + nt * 8 + t4 * 2;
            *(float2*)&g_V[(size_t)m * 4096 + n]       = make_float2(acc[mt][nt][0], acc[mt][nt][1]);
            *(float2*)&g_V[(size_t)(m + 8) * 4096 + n] = make_float2(acc[mt][nt][2], acc[mt][nt][3]);
        }
    }
}

// ---- Kernel 2: LN + LSTM + LN, 128 threads x 8 elems ------------------------

__device__ __forceinline__ float sigm(float v) {
    return __fdividef(1.f, 1.f + __expf(-v));
}
__device__ __forceinline__ float tanh_f(float v) {
    return fmaf(2.f, sigm(2.f * v), -1.f);
}
__device__ __forceinline__ float sum4(float4 v) { return v.x + v.y + v.z + v.w; }
__device__ __forceinline__ float sq4(float4 v) {
    return v.x * v.x + v.y * v.y + v.z * v.z + v.w * v.w;
}

__global__ __launch_bounds__(128)
void ln_lstm(const float* __restrict__ c,
             const float* __restrict__ b_ih,
             const float* __restrict__ gamma_ifgo, const float* __restrict__ beta_ifgo,
             const float* __restrict__ gamma_c,    const float* __restrict__ beta_c,
             float* __restrict__ out) {
    __shared__ float red[4][8];
    __shared__ float red2[4][2];

    const int b   = blockIdx.x;
    const int tid = threadIdx.x;            // 0..127; owns 8 H-elems
    const int w   = tid >> 5;

    const float4* vb   = (const float4*)(g_V + (size_t)b * 4096);
    const float4* bih4 = (const float4*)b_ih;

    float4 wv[4][2];
    float  s[4], ss[4];
    #pragma unroll
    for (int g = 0; g < 4; g++) {
        float4 t0 = vb[g * 256 + tid * 2];
        float4 t1 = vb[g * 256 + tid * 2 + 1];
        float4 b0 = bih4[g * 256 + tid * 2];
        float4 b1 = bih4[g * 256 + tid * 2 + 1];
        t0.x += b0.x; t0.y += b0.y; t0.z += b0.z; t0.w += b0.w;
        t1.x += b1.x; t1.y += b1.y; t1.z += b1.z; t1.w += b1.w;
        wv[g][0] = t0; wv[g][1] = t1;
        s[g]  = sum4(t0) + sum4(t1);
        ss[g] = sq4(t0) + sq4(t1);
    }
    #pragma unroll
    for (int o = 16; o > 0; o >>= 1) {
        #pragma unroll
        for (int g = 0; g < 4; g++) {
            s[g]  += __shfl_xor_sync(0xffffffffu, s[g],  o);
            ss[g] += __shfl_xor_sync(0xffffffffu, ss[g], o);
        }
    }
    if ((tid & 31) == 0) {
        #pragma unroll
        for (int g = 0; g < 4; g++) { red[w][g * 2] = s[g]; red[w][g * 2 + 1] = ss[g]; }
    }
    __syncthreads();

    float4 gate[4][2];
    #pragma unroll
    for (int g = 0; g < 4; g++) {
        float S  = red[0][g * 2]     + red[1][g * 2]     + red[2][g * 2]     + red[3][g * 2];
        float SS = red[0][g * 2 + 1] + red[1][g * 2 + 1] + red[2][g * 2 + 1] + red[3][g * 2 + 1];
        float mean = S * (1.f / 1024.f);
        float var  = fmaxf(SS - S * mean, 0.f) * (1.f / 1023.f);
        float inv  = 1.f / (sqrtf(var) + 1e-6f);
        #pragma unroll
        for (int q = 0; q < 2; q++) {
            float4 ga = ((const float4*)gamma_ifgo)[g * 256 + tid * 2 + q];
            float4 be = ((const float4*)beta_ifgo)[g * 256 + tid * 2 + q];
            float4 t  = wv[g][q];
            gate[g][q].x = ga.x * (t.x - mean) * inv + be.x;
            gate[g][q].y = ga.y * (t.y - mean) * inv + be.y;
            gate[g][q].z = ga.z * (t.z - mean) * inv + be.z;
            gate[g][q].w = ga.w * (t.w - mean) * inv + be.w;
        }
    }

    float4 cc[2];
    float s2 = 0.f, ss2 = 0.f;
    #pragma unroll
    for (int q = 0; q < 2; q++) {
        float4 ci = ((const float4*)(c + (size_t)b * 1024))[tid * 2 + q];
        float4 v;
        v.x = ci.x * sigm(gate[1][q].x + 1.f) + sigm(gate[0][q].x) * tanh_f(gate[2][q].x);
        v.y = ci.y * sigm(gate[1][q].y + 1.f) + sigm(gate[0][q].y) * tanh_f(gate[2][q].y);
        v.z = ci.z * sigm(gate[1][q].z + 1.f) + sigm(gate[0][q].z) * tanh_f(gate[2][q].z);
        v.w = ci.w * sigm(gate[1][q].w + 1.f) + sigm(gate[0][q].w) * tanh_f(gate[2][q].w);
        cc[q] = v;
        s2  += sum4(v);
        ss2 += sq4(v);
    }
    #pragma unroll
    for (int o = 16; o > 0; o >>= 1) {
        s2  += __shfl_xor_sync(0xffffffffu, s2,  o);
        ss2 += __shfl_xor_sync(0xffffffffu, ss2, o);
    }
    if ((tid & 31) == 0) { red2[w][0] = s2; red2[w][1] = ss2; }
    __syncthreads();
    float S  = red2[0][0] + red2[1][0] + red2[2][0] + red2[3][0];
    float SS = red2[0][1] + red2[1][1] + red2[2][1] + red2[3][1];
    float mean = S * (1.f / 1024.f);
    float var  = fmaxf(SS - S * mean, 0.f) * (1.f / 1023.f);
    float inv  = 1.f / (sqrtf(var) + 1e-6f);

    #pragma unroll
    for (int q = 0; q < 2; q++) {
        float4 gc = ((const float4*)gamma_c)[tid * 2 + q];
        float4 bc = ((const float4*)beta_c)[tid * 2 + q];
        float4 nc, nh;
        nc.x = gc.x * (cc[q].x - mean) * inv + bc.x;  nh.x = tanh_f(nc.x) * sigm(gate[3][q].x);
        nc.y = gc.y * (cc[q].y - mean) * inv + bc.y;  nh.y = tanh_f(nc.y) * sigm(gate[3][q].y);
        nc.z = gc.z * (cc[q].z - mean) * inv + bc.z;  nh.z = tanh_f(nc.z) * sigm(gate[3][q].z);
        nc.w = gc.w * (cc[q].w - mean) * inv + bc.w;  nh.w = tanh_f(nc.w) * sigm(gate[3][q].w);
        ((float4*)out)[(size_t)b * 256 + tid * 2 + q]                      = nh;
        ((float4*)out)[(size_t)4096 * 256 + (size_t)b * 256 + tid * 2 + q] = nc;
    }
}

// ---- launch ----------------------------------------------------------------

extern "C" void kernel_launch(void* const* d_in, const int* in_sizes, int n_in,
                              void* d_out, int out_size) {
    const float* x     = (const float*)d_in[0];
    const float* h     = (const float*)d_in[1];
    const float* c     = (const float*)d_in[2];
    const float* Wih   = (const float*)d_in[3];
    const float* bih   = (const float*)d_in[4];
    const float* Whh   = (const float*)d_in[5];
    const float* gifgo = (const float*)d_in[6];
    const float* bifgo = (const float*)d_in[7];
    const float* gc    = (const float*)d_in[8];
    const float* bc    = (const float*)d_in[9];
    float* out = (float*)d_out;

    __half *gA, *gW;
    cudaGetSymbolAddress((void**)&gA, g_A);
    cudaGetSymbolAddress((void**)&gW, g_W);

    cudaFuncSetAttribute(gemm_f16, cudaFuncAttributeMaxDynamicSharedMemorySize, SMEM_SZ);

    tohalf<<<8192, 256>>>(x, h, Wih, Whh);
    dim3 grid(4096 / BN, 4096 / BM);            // 32 x 32
    gemm_f16<<<grid, 256, SMEM_SZ>>>(gA, gW);
    ln_lstm<<<4096, 128>>>(c, bih, gifgo, bifgo, gc, bc, out);
}